// round 2
// baseline (speedup 1.0000x reference)
#include <cuda_runtime.h>
#include <cstdint>

// ---------------------------------------------------------------------------
// QuantizerEncoder: code[n,h,w,m] = argmax_k  x[p,m,:] . M[m][:,k]
// where M[m] = wq[m]^T @ (wk[m] @ cb[m]^T)   (fused projection, [128,256])
//
// Inputs (metadata order):
//   d_in[0] latent  f32 [16,512,64,64]
//   d_in[1] codebook f32 [4,256,128]
//   d_in[2] wq      f32 [4,128,128]
//   d_in[3] wk      f32 [4,128,128]
// Output: 262144 elements [n,h,w,m] — written as float32 (code index value);
// round-1 evidence: harness reads d_out as float (uint8 writes produced NaNs).
// ---------------------------------------------------------------------------

typedef unsigned long long ULL;

// Scratch (static __device__ arrays: no allocation allowed)
__device__ float g_keys[4 * 256 * 128];   // keys[m][k][c]
__device__ float g_mdup[4 * 128 * 512];   // M duplicated along k: [m][d][2k],[2k+1]

// ---- setup kernel 1: keys[m][k][c] = sum_d cb[m][k][d] * wk[m][c][d] ----
__global__ void keys_kernel(const float* __restrict__ cb,
                            const float* __restrict__ wk) {
    int m = blockIdx.y, k = blockIdx.x, t = threadIdx.x;  // t = c
    __shared__ float scb[128];
    scb[t] = cb[(m * 256 + k) * 128 + t];
    __syncthreads();
    const float* wrow = wk + (size_t)(m * 128 + t) * 128;
    float s = 0.f;
#pragma unroll 8
    for (int d = 0; d < 128; d++) s += scb[d] * __ldg(&wrow[d]);
    g_keys[(m * 256 + k) * 128 + t] = s;
}

// ---- setup kernel 2: M[m][d][k] = sum_c wq[m][c][d] * keys[m][k][c], dup'd ----
__global__ void mmat_kernel(const float* __restrict__ wq) {
    int m = blockIdx.y, k = blockIdx.x, t = threadIdx.x;  // t = d
    __shared__ float sk[128];
    sk[t] = g_keys[(m * 256 + k) * 128 + t];
    __syncthreads();
    const float* wbase = wq + (size_t)m * 128 * 128 + t;
    float s = 0.f;
#pragma unroll 8
    for (int c = 0; c < 128; c++) s += wbase[c * 128] * sk[c];
    float* o = g_mdup + (size_t)(m * 128 + t) * 512 + 2 * k;
    o[0] = s;
    o[1] = s;
}

// ---- main kernel: scores + argmax ----
// Block: 256 threads (tx = tid&15 -> k dim, ty = tid>>4 -> pixel dim)
// Block tile: 128 pixels x 128 k per chunk (2 chunks cover K=256)
// Thread tile: 8 pixels x 8 k, FFMA2-paired over pixels.
// Smem: x tile [128 d][128 p] (64KB) + M chunk permuted [32 d][256] (32KB)
__global__ __launch_bounds__(256, 2)
void score_kernel(const float* __restrict__ latent, float* __restrict__ out) {
    extern __shared__ float smem[];
    float* sx = smem;               // 128*128 floats
    float* sm = smem + 128 * 128;   // 32*256 floats (permuted dup'd M chunk)

    const int t = threadIdx.x;
    const int tx = t & 15;          // k-group
    const int ty = t >> 4;          // pixel-group
    const int bp = blockIdx.x;      // 0..511 pixel tile
    const int m = blockIdx.y;       // 0..3 group
    const int n = bp >> 5;
    const int p0 = (bp & 31) << 7;  // pixel offset within n (hw space 4096)

    const float* xbase = latent + ((size_t)(n * 512 + m * 128)) * 4096 + p0;

    // Load x tile [d][p]  (16384 floats = 4096 float4, 16 per thread)
#pragma unroll
    for (int i = 0; i < 16; i++) {
        int j = i * 256 + t;        // float4 id
        int d = j >> 5, p4 = j & 31;
        ((float4*)sx)[d * 32 + p4] =
            __ldg((const float4*)(xbase + (size_t)d * 4096) + p4);
    }

    float bestv[8];
    int besti[8];
#pragma unroll
    for (int pl = 0; pl < 8; pl++) { bestv[pl] = -3.4e38f; besti[pl] = 0; }

    const float4* mg = (const float4*)g_mdup;

    for (int kc = 0; kc < 2; kc++) {
        ULL acc[4][8];
#pragma unroll
        for (int pp = 0; pp < 4; pp++)
#pragma unroll
            for (int kk = 0; kk < 8; kk++) acc[pp][kk] = 0ULL;

        for (int dc = 0; dc < 4; dc++) {
            __syncthreads();
            // Stage dup'd M chunk rows [dc*32 .. +31], cols [kc*256 .. +255],
            // permuted so inner-loop LDS.128 is phase-conflict-free:
            // smem float4 slot = r*64 + q*16 + txm  holds  global col4 = txm*4+q
#pragma unroll
            for (int i = 0; i < 8; i++) {
                int j = i * 256 + t;          // float4 id, 2048 total
                int r = j >> 6, c4 = j & 63;
                int txm = c4 >> 2, q = c4 & 3;
                ((float4*)sm)[r * 64 + q * 16 + txm] =
                    mg[(size_t)(m * 128 + dc * 32 + r) * 128 + kc * 64 + c4];
            }
            __syncthreads();

#pragma unroll 2
            for (int dd = 0; dd < 32; dd++) {
                int d = dc * 32 + dd;
                // a: 8 pixels as 4 f32x2 pairs
                ulonglong2 A0 = *(const ulonglong2*)(sx + d * 128 + ty * 8);
                ulonglong2 A1 = *(const ulonglong2*)(sx + d * 128 + ty * 8 + 4);
                ULL a[4] = {A0.x, A0.y, A1.x, A1.y};
                // b: 8 dup'd M values (m_k, m_k) via 4 LDS.128
                ULL b[8];
#pragma unroll
                for (int q = 0; q < 4; q++) {
                    ulonglong2 B =
                        *(const ulonglong2*)(sm + dd * 256 + (q * 16 + tx) * 4);
                    b[2 * q] = B.x;
                    b[2 * q + 1] = B.y;
                }
#pragma unroll
                for (int kk = 0; kk < 8; kk++)
#pragma unroll
                    for (int pp = 0; pp < 4; pp++)
                        asm("fma.rn.f32x2 %0, %1, %2, %0;"
                            : "+l"(acc[pp][kk])
                            : "l"(a[pp]), "l"(b[kk]));
            }
        }

        // Merge this k-chunk into running argmax (ascending k => strict '>'
        // keeps the earliest index on ties, matching jnp.argmax)
#pragma unroll
        for (int kk = 0; kk < 8; kk++) {
            int kg = kc * 128 + tx * 8 + kk;
#pragma unroll
            for (int pp = 0; pp < 4; pp++) {
                float lo = __uint_as_float((unsigned)(acc[pp][kk] & 0xffffffffu));
                float hi = __uint_as_float((unsigned)(acc[pp][kk] >> 32));
                if (lo > bestv[2 * pp])     { bestv[2 * pp] = lo;     besti[2 * pp] = kg; }
                if (hi > bestv[2 * pp + 1]) { bestv[2 * pp + 1] = hi; besti[2 * pp + 1] = kg; }
            }
        }
    }

    // Cross-tx (16 lanes) argmax reduce; pack sortable-float + (255-idx)
#pragma unroll
    for (int pl = 0; pl < 8; pl++) {
        unsigned ub = __float_as_uint(bestv[pl]);
        ub = (ub & 0x80000000u) ? ~ub : (ub | 0x80000000u);
        ULL key = ((ULL)ub << 32) | (unsigned)(255 - besti[pl]);
#pragma unroll
        for (int o = 8; o >= 1; o >>= 1) {
            ULL other = __shfl_xor_sync(0xffffffffu, key, o, 16);
            if (other > key) key = other;
        }
        if (tx == 0) {
            int idx = 255 - (int)(key & 0xff);
            int pix = n * 4096 + p0 + ty * 8 + pl;
            out[pix * 4 + m] = (float)idx;   // output dtype is float (round-1 evidence)
        }
    }
}

extern "C" void kernel_launch(void* const* d_in, const int* in_sizes, int n_in,
                              void* d_out, int out_size) {
    const float* latent = (const float*)d_in[0];
    const float* cb     = (const float*)d_in[1];
    const float* wq     = (const float*)d_in[2];
    const float* wk     = (const float*)d_in[3];

    cudaFuncSetAttribute(score_kernel,
                         cudaFuncAttributeMaxDynamicSharedMemorySize, 98304);

    keys_kernel<<<dim3(256, 4), 128>>>(cb, wk);
    mmat_kernel<<<dim3(256, 4), 128>>>(wq);
    score_kernel<<<dim3(512, 4), 256, 98304>>>(latent, (float*)d_out);
}

// round 4
// speedup vs baseline: 1.3221x; 1.3221x over previous
#include <cuda_runtime.h>
#include <cstdint>

// ---------------------------------------------------------------------------
// QuantizerEncoder via mma.sync tf32 (2-way split, 3 passes) — sm_103 fallback
// HMMA path (tcgen05 is rejected by this build's ptxas target).
//
//   score[code][px] = sum_d Mmat[code][d] * x[d][px]
//   Mmat[k][d] = sum_c wq[c][d]*keys[k][c];  keys[k][c] = sum_d cb[k][d]*wk[c][d]
//   out[n,h,w,m] = argmax_code score  (written as float, per round-1 evidence)
//
// A: prebuilt in global in m16n8k8 per-thread frag layout (tf32 hi/lo), L2-res.
// B: per-CTA smem, frag-linear layout, tf32 hi/lo (128KB).
// ---------------------------------------------------------------------------

typedef unsigned long long ULL;

__device__ float g_keys[4 * 256 * 128];   // [m][k][c]
__device__ float g_A[262144];             // [m][half][mtile][ks][split][lane*4+i]

static __device__ __forceinline__ uint32_t f2tf32(float v) {
    uint32_t u;
    asm("cvt.rna.tf32.f32 %0, %1;" : "=r"(u) : "f"(v));
    return u;
}

static __device__ __forceinline__ void mma8(float* d, float4 a, float2 b) {
    asm volatile(
        "mma.sync.aligned.m16n8k8.row.col.f32.tf32.tf32.f32 "
        "{%0,%1,%2,%3}, {%4,%5,%6,%7}, {%8,%9}, {%0,%1,%2,%3};"
        : "+f"(d[0]), "+f"(d[1]), "+f"(d[2]), "+f"(d[3])
        : "r"(__float_as_uint(a.x)), "r"(__float_as_uint(a.y)),
          "r"(__float_as_uint(a.z)), "r"(__float_as_uint(a.w)),
          "r"(__float_as_uint(b.x)), "r"(__float_as_uint(b.y)));
}

// ---------------- setup 1: keys[m][k][c] = sum_d cb[m][k][d]*wk[m][c][d] ----
__global__ __launch_bounds__(256, 1)
void keys_kernel(const float* __restrict__ cb, const float* __restrict__ wk) {
    extern __shared__ float sm[];
    float* swkT = sm;            // [128 d][129] transposed wk
    float* scb = sm + 129 * 128; // [32 k][128 d]
    const int m = blockIdx.y, kch = blockIdx.x, t = threadIdx.x;

    const float4* wk4 = (const float4*)(wk + (size_t)m * 16384);
#pragma unroll
    for (int i = 0; i < 16; i++) {
        int j = i * 256 + t, c = j >> 5, d4 = j & 31;
        float4 v = __ldg(wk4 + j);
        swkT[(4 * d4 + 0) * 129 + c] = v.x;
        swkT[(4 * d4 + 1) * 129 + c] = v.y;
        swkT[(4 * d4 + 2) * 129 + c] = v.z;
        swkT[(4 * d4 + 3) * 129 + c] = v.w;
    }
    const float4* cb4 = (const float4*)(cb + ((size_t)m * 256 + kch * 32) * 128);
#pragma unroll
    for (int i = 0; i < 4; i++) ((float4*)scb)[i * 256 + t] = __ldg(cb4 + i * 256 + t);
    __syncthreads();
#pragma unroll
    for (int i = 0; i < 16; i++) {
        int o = i * 256 + t, kl = o >> 7, c = o & 127;
        float s = 0.f;
#pragma unroll 8
        for (int d = 0; d < 128; d++) s += scb[kl * 128 + d] * swkT[d * 129 + c];
        g_keys[((size_t)m * 256 + kch * 32 + kl) * 128 + c] = s;
    }
}

// ---------------- setup 2: Mmat -> tf32 hi/lo in HMMA frag layout -----------
__global__ __launch_bounds__(256, 1)
void mmat_kernel(const float* __restrict__ wq) {
    extern __shared__ float sm[];
    float* swq = sm;             // [128 c][128 d]
    float* skeys = sm + 16384;   // [32 k][128 c]
    const int m = blockIdx.y, kch = blockIdx.x, t = threadIdx.x;

    const float4* wq4 = (const float4*)(wq + (size_t)m * 16384);
#pragma unroll
    for (int i = 0; i < 16; i++) ((float4*)swq)[i * 256 + t] = __ldg(wq4 + i * 256 + t);
    const float4* ks4 = (const float4*)(g_keys + ((size_t)m * 256 + kch * 32) * 128);
#pragma unroll
    for (int i = 0; i < 4; i++) ((float4*)skeys)[i * 256 + t] = ks4[i * 256 + t];
    __syncthreads();
#pragma unroll
    for (int i = 0; i < 16; i++) {
        int o = i * 256 + t, kl = o >> 7, d = o & 127;
        float val = 0.f;
#pragma unroll 8
        for (int c = 0; c < 128; c++) val += swq[c * 128 + d] * skeys[kl * 128 + c];
        uint32_t hib = f2tf32(val);
        float lo = val - __uint_as_float(hib);
        uint32_t lob = f2tf32(lo);

        int k = kch * 32 + kl;
        int half = k >> 7, kr = k & 127, w = kr >> 4, r = kr & 15;
        int ks = d >> 3, dc = d & 7;
        int ln, fi;
        if (r < 8) { ln = r * 4 + (dc & 3); fi = (dc >= 4) ? 2 : 0; }
        else       { ln = (r - 8) * 4 + (dc & 3); fi = (dc >= 4) ? 3 : 1; }
        size_t base = (size_t)((((m * 2 + half) * 8 + w) * 16 + ks) * 2) * 128 + ln * 4 + fi;
        g_A[base] = __uint_as_float(hib);        // split 0 (hi)
        g_A[base + 128] = __uint_as_float(lob);  // split 1 (lo)
    }
}

// ---------------- main: HMMA tf32-split score + fused argmax ----------------
// CTA: 256 threads, 128 px, one m. grid = (512, 4) = 2048 CTAs.
// smem: B hi [16384 f] + B lo [16384 f] + keys ULL[16*128]  = 147456 B.
// B frag-linear: float idx = ((j*8 + sp)*32 + lane)*4 + (w1*2 + hi4bit)
//   for element (d, px): j=px>>3, sp=d>>4, w1=(d>>3)&1, lane=((px&7)<<2)|(d&3)
__global__ __launch_bounds__(256, 1)
void score_kernel(const float* __restrict__ latent, float* __restrict__ out) {
    extern __shared__ float sb[];
    ULL* keys = (ULL*)(sb + 32768);

    const int t = threadIdx.x, lane = t & 31, wid = t >> 5;
    const int m = blockIdx.y;
    const int n = blockIdx.x >> 5;
    const int p0 = (blockIdx.x & 31) << 7;   // 128 px per CTA

    // ---- convert latent [128 d][128 px] -> tf32 hi/lo in frag layout ----
    const float* xb = latent + ((size_t)(n * 512 + m * 128)) * 4096 + p0;
#pragma unroll
    for (int i = 0; i < 16; i++) {
        int idx = i * 256 + t;
        int d = idx >> 5, p4 = idx & 31;
        float4 v = __ldg((const float4*)(xb + (size_t)d * 4096) + p4);
        float e[4] = {v.x, v.y, v.z, v.w};
        int sp = d >> 4, w1 = (d >> 3) & 1;
        int ee = w1 * 2 + ((d & 4) ? 1 : 0);
#pragma unroll
        for (int q = 0; q < 4; q++) {
            int c = (t + q) & 3;             // rotate to spread smem banks
            int px = p4 * 4 + c;
            float val = e[c];
            uint32_t hib = f2tf32(val);
            uint32_t lob = f2tf32(val - __uint_as_float(hib));
            int j = px >> 3;
            int ln = ((px & 7) << 2) | (d & 3);
            int off = ((j * 8 + sp) * 32 + ln) * 4 + ee;
            sb[off] = __uint_as_float(hib);
            sb[16384 + off] = __uint_as_float(lob);
        }
    }
    __syncthreads();

    for (int half = 0; half < 2; half++) {
        float acc[16][4];
#pragma unroll
        for (int j = 0; j < 16; j++)
#pragma unroll
            for (int c = 0; c < 4; c++) acc[j][c] = 0.f;

        const float4* pA = ((const float4*)g_A) +
                           (size_t)((m * 2 + half) * 8 + wid) * 1024;

#pragma unroll 2
        for (int ks = 0; ks < 16; ks++) {
            float4 ah = __ldg(pA + ks * 64 + lane);
            float4 al = __ldg(pA + ks * 64 + 32 + lane);
            int sp = ks >> 1, w1 = ks & 1;
#pragma unroll
            for (int j = 0; j < 16; j++) {
                int f = ((j * 8 + sp) * 32 + lane) * 4 + w1 * 2;
                float2 bh = *(const float2*)(sb + f);
                float2 bl = *(const float2*)(sb + 16384 + f);
                mma8(acc[j], ah, bh);
                mma8(acc[j], ah, bl);
                mma8(acc[j], al, bh);
            }
        }

        // ---- fused argmax over this warp's 16 codes ----
        int r0 = half * 128 + wid * 16 + (lane >> 2);
#pragma unroll
        for (int j = 0; j < 16; j++) {
#pragma unroll
            for (int cc = 0; cc < 2; cc++) {
                float v0 = acc[j][cc];       // code r0
                float v1 = acc[j][2 + cc];   // code r0+8
                float bv; int bc;
                if (v1 > v0) { bv = v1; bc = r0 + 8; } else { bv = v0; bc = r0; }
                unsigned ub = __float_as_uint(bv);
                ub = (ub & 0x80000000u) ? ~ub : (ub | 0x80000000u);
                ULL key = ((ULL)ub << 32) | (unsigned)(255 - bc);
#pragma unroll
                for (int o = 4; o <= 16; o <<= 1) {
                    ULL other = __shfl_xor_sync(0xffffffffu, key, o);
                    if (other > key) key = other;
                }
                if (lane < 4) {
                    int px = j * 8 + (lane & 3) * 2 + cc;
                    keys[(half * 8 + wid) * 128 + px] = key;
                }
            }
        }
    }
    __syncthreads();

    if (t < 128) {
        ULL best = keys[t];
#pragma unroll
        for (int g = 1; g < 16; g++) {
            ULL o = keys[g * 128 + t];
            if (o > best) best = o;
        }
        int code = 255 - (int)(best & 0xFF);
        int pix = n * 4096 + p0 + t;
        out[pix * 4 + m] = (float)code;
    }
}

extern "C" void kernel_launch(void* const* d_in, const int* in_sizes, int n_in,
                              void* d_out, int out_size) {
    const float* latent = (const float*)d_in[0];
    const float* cb     = (const float*)d_in[1];
    const float* wq     = (const float*)d_in[2];
    const float* wk     = (const float*)d_in[3];

    cudaFuncSetAttribute(keys_kernel, cudaFuncAttributeMaxDynamicSharedMemorySize, 83456);
    cudaFuncSetAttribute(mmat_kernel, cudaFuncAttributeMaxDynamicSharedMemorySize, 81920);
    cudaFuncSetAttribute(score_kernel, cudaFuncAttributeMaxDynamicSharedMemorySize, 147456);

    keys_kernel<<<dim3(8, 4), 256, 83456>>>(cb, wk);
    mmat_kernel<<<dim3(8, 4), 256, 81920>>>(wq);
    score_kernel<<<dim3(512, 4), 256, 147456>>>(latent, (float*)d_out);
}